// round 3
// baseline (speedup 1.0000x reference)
#include <cuda_runtime.h>
#include <math.h>

// Problem constants (fixed by the reference)
#define NN      64
#define GRID_N  (NN * NN * NN)   // 262144
#define NQ      200
#define BATCH   2

__global__ void ibl_zero_out(float* out) {
    out[0] = 0.0f;
}

__global__ __launch_bounds__(256)
void ibl_loss_kernel(const float* __restrict__ field,    // (BATCH,1,64,64,64)
                     const float* __restrict__ q,        // (NQ,)
                     const float* __restrict__ xq,       // (NQ,3)
                     const float* __restrict__ points,   // (GRID_N,3)
                     const int*   __restrict__ xi,
                     const int*   __restrict__ yi,
                     const int*   __restrict__ zi,
                     const float* __restrict__ normals,  // (NB,3)
                     int nb,
                     float* __restrict__ out)
{
    __shared__ float4 sq[NQ];   // {xq.x, xq.y, xq.z, q}

    const float EPSF   = 1.1920929e-07f;               // np.finfo(float32).eps
    const float INV4PI = 1.0f / (4.0f * 3.14159265358979323846f);
    const float DXF    = (float)(1.0 / 63.0);          // DX in fp32, matching jnp weak-type f32 div

    const int tid = threadIdx.x;

    // Stage charges into shared memory
    for (int k = tid; k < NQ; k += blockDim.x) {
        sq[k] = make_float4(xq[3 * k + 0], xq[3 * k + 1], xq[3 * k + 2], q[k]);
    }
    __syncthreads();

    const int i = blockIdx.x * blockDim.x + tid;
    float local = 0.0f;

    if (i < nb) {
        const int x = xi[i], y = yi[i], z = zi[i];
        const int flat = (x * NN + y) * NN + z;

        // Exact grid-point coordinates (match reference's fp64->fp32 points)
        const float px = points[3 * flat + 0];
        const float py = points[3 * flat + 1];
        const float pz = points[3 * flat + 2];

        // Green's function + gradient at this boundary point over all charges
        float g = 0.0f, gx = 0.0f, gy = 0.0f, gz = 0.0f;
        #pragma unroll 4
        for (int k = 0; k < NQ; k++) {
            const float4 c = sq[k];
            const float dx = px - c.x;
            const float dy = py - c.y;
            const float dz = pz - c.z;
            const float r2 = fmaf(dx, dx, fmaf(dy, dy, dz * dz));
            // r==0 -> r=EPS in the reference; grad term is coef*0 = 0 either way.
            const float inv_r  = (r2 > 0.0f) ? rsqrtf(r2) : (1.0f / EPSF);
            g = fmaf(c.w, inv_r, g);
            const float inv_r3 = inv_r * inv_r * inv_r;   // 1/r^3
            const float coef   = -c.w * inv_r3;
            gx = fmaf(coef, dx, gx);
            gy = fmaf(coef, dy, gy);
            gz = fmaf(coef, dz, gz);
        }
        g  *= INV4PI;
        gx *= INV4PI;
        gy *= INV4PI;
        gz *= INV4PI;

        const float nx = normals[3 * i + 0];
        const float ny = normals[3 * i + 1];
        const float nz = normals[3 * i + 2];
        const float gcnd = gx * nx + gy * ny + gz * nz;

        // loss1: (mol_b - out_b)^2 == g^2, identical for both batches
        local = (float)BATCH * (g * g);

        // loss2: one-sided normal derivatives per batch (7-point stencil)
        #pragma unroll
        for (int b = 0; b < BATCH; b++) {
            const float* __restrict__ o = field + b * GRID_N;
            const float c0  = o[flat];
            const float lft = o[flat - NN * NN];   // x-1
            const float rgt = o[flat + NN * NN];   // x+1
            const float bel = o[flat - NN];        // y-1
            const float abv = o[flat + NN];        // y+1
            const float bck = o[flat - 1];         // z-1
            const float frt = o[flat + 1];         // z+1

            const float dmx = (c0 - lft) / DXF;    // backward diff
            const float dpx = (rgt - c0) / DXF;    // forward diff
            const float dmy = (c0 - bel) / DXF;
            const float dpy = (abv - c0) / DXF;
            const float dmz = (c0 - bck) / DXF;
            const float dpz = (frt - c0) / DXF;

            const float gx_in  = (nx > 0.0f) ? dmx : dpx;
            const float gx_out = (nx > 0.0f) ? dpx : dmx;
            const float gy_in  = (ny > 0.0f) ? dmy : dpy;
            const float gy_out = (ny > 0.0f) ? dpy : dmy;
            const float gz_in  = (nz > 0.0f) ? dmz : dpz;
            const float gz_out = (nz > 0.0f) ? dpz : dmz;

            const float nd_in  = gx_in  * nx + gy_in  * ny + gz_in  * nz;
            const float nd_out = gx_out * nx + gy_out * ny + gz_out * nz;

            // E_IN = 1, E_OUT = 80
            const float t = (nd_in + gcnd) - 80.0f * nd_out;
            local = fmaf(t, t, local);
        }
    }

    // Block reduction: warp shuffle, then cross-warp via shared
    float v = local;
    #pragma unroll
    for (int off = 16; off > 0; off >>= 1)
        v += __shfl_down_sync(0xffffffffu, v, off);

    __shared__ float wsum[8];
    const int warp = tid >> 5;
    const int lane = tid & 31;
    if (lane == 0) wsum[warp] = v;
    __syncthreads();

    if (warp == 0) {
        v = (lane < (int)(blockDim.x >> 5)) ? wsum[lane] : 0.0f;
        #pragma unroll
        for (int off = 4; off > 0; off >>= 1)
            v += __shfl_down_sync(0xffffffffu, v, off);
        if (lane == 0) {
            const float inv_den = 1.0f / (float)(BATCH * nb);  // mean over (batch, NB), twice
            atomicAdd(out, v * inv_den);
        }
    }
}

extern "C" void kernel_launch(void* const* d_in, const int* in_sizes, int n_in,
                              void* d_out, int out_size)
{
    const float* field   = (const float*)d_in[0];  // output (2,1,64,64,64)
    const float* q       = (const float*)d_in[1];  // (200,)
    const float* xq      = (const float*)d_in[2];  // (200,3)
    const float* points  = (const float*)d_in[3];  // (262144,3)
    const int*   xi      = (const int*)  d_in[4];
    const int*   yi      = (const int*)  d_in[5];
    const int*   zi      = (const int*)  d_in[6];
    const float* normals = (const float*)d_in[7];  // (NB,3)
    float*       out     = (float*)d_out;

    const int nb = in_sizes[4];

    ibl_zero_out<<<1, 1>>>(out);

    const int threads = 256;
    const int blocks  = (nb + threads - 1) / threads;
    ibl_loss_kernel<<<blocks, threads>>>(field, q, xq, points,
                                         xi, yi, zi, normals, nb, out);
}

// round 4
// speedup vs baseline: 1.4984x; 1.4984x over previous
#include <cuda_runtime.h>
#include <math.h>

// Problem constants (fixed by the reference)
#define NN      64
#define GRID_N  (NN * NN * NN)   // 262144
#define NQ      200
#define BATCH   2
#define CH      8                // threads cooperating per boundary point
#define QPT     (NQ / CH)        // 25 charges per thread

__global__ __launch_bounds__(256)
void ibl_loss_kernel(const float* __restrict__ field,    // (BATCH,1,64,64,64)
                     const float* __restrict__ q,        // (NQ,)
                     const float* __restrict__ xq,       // (NQ,3)
                     const float* __restrict__ points,   // (GRID_N,3)
                     const int*   __restrict__ xi,
                     const int*   __restrict__ yi,
                     const int*   __restrict__ zi,
                     const float* __restrict__ normals,  // (NB,3)
                     int nb,
                     float* __restrict__ out)
{
    __shared__ float4 sq[NQ];   // {xq.x, xq.y, xq.z, q}

    const float EPSF   = 1.1920929e-07f;               // np.finfo(float32).eps
    const float INV4PI = 1.0f / (4.0f * 3.14159265358979323846f);
    const float DXF    = (float)(1.0 / 63.0);

    const int tid = threadIdx.x;

    // Stage charges into shared memory (one float4 per thread, 200 <= 256)
    if (tid < NQ) {
        sq[tid] = make_float4(xq[3 * tid + 0], xq[3 * tid + 1], xq[3 * tid + 2], q[tid]);
    }
    __syncthreads();

    const int gtid = blockIdx.x * blockDim.x + tid;
    const int i = gtid >> 3;        // boundary point index
    const int c = gtid & (CH - 1);  // charge-chunk index within point

    float g = 0.0f, gx = 0.0f, gy = 0.0f, gz = 0.0f;
    int flat = 0;

    if (i < nb) {
        const int x = xi[i], y = yi[i], z = zi[i];
        flat = (x * NN + y) * NN + z;

        // Exact grid-point coordinates (match reference's fp64->fp32 points)
        const float px = points[3 * flat + 0];
        const float py = points[3 * flat + 1];
        const float pz = points[3 * flat + 2];

        const int k0 = c * QPT;
        #pragma unroll
        for (int kk = 0; kk < QPT; kk++) {
            const float4 ch = sq[k0 + kk];
            const float dx = px - ch.x;
            const float dy = py - ch.y;
            const float dz = pz - ch.z;
            const float r2 = fmaf(dx, dx, fmaf(dy, dy, dz * dz));
            // r==0 -> r=EPS in the reference; grad term is coef*0 = 0 either way.
            const float inv_r  = (r2 > 0.0f) ? rsqrtf(r2) : (1.0f / EPSF);
            g = fmaf(ch.w, inv_r, g);
            const float inv_r3 = inv_r * inv_r * inv_r;
            const float coef   = -ch.w * inv_r3;
            gx = fmaf(coef, dx, gx);
            gy = fmaf(coef, dy, gy);
            gz = fmaf(coef, dz, gz);
        }
    }

    // Reduce the 4 accumulators across the 8-thread group (width-8 shuffles)
    #pragma unroll
    for (int off = CH / 2; off > 0; off >>= 1) {
        g  += __shfl_down_sync(0xffffffffu, g,  off, CH);
        gx += __shfl_down_sync(0xffffffffu, gx, off, CH);
        gy += __shfl_down_sync(0xffffffffu, gy, off, CH);
        gz += __shfl_down_sync(0xffffffffu, gz, off, CH);
    }

    float local = 0.0f;
    if (c == 0 && i < nb) {
        g  *= INV4PI;
        gx *= INV4PI;
        gy *= INV4PI;
        gz *= INV4PI;

        const float nx = normals[3 * i + 0];
        const float ny = normals[3 * i + 1];
        const float nz = normals[3 * i + 2];
        const float gcnd = gx * nx + gy * ny + gz * nz;

        // loss1: (mol_b - out_b)^2 == g^2, identical for both batches
        local = (float)BATCH * (g * g);

        // loss2: one-sided normal derivatives per batch (7-point stencil)
        #pragma unroll
        for (int b = 0; b < BATCH; b++) {
            const float* __restrict__ o = field + b * GRID_N;
            const float c0  = o[flat];
            const float lft = o[flat - NN * NN];   // x-1
            const float rgt = o[flat + NN * NN];   // x+1
            const float bel = o[flat - NN];        // y-1
            const float abv = o[flat + NN];        // y+1
            const float bck = o[flat - 1];         // z-1
            const float frt = o[flat + 1];         // z+1

            const float dmx = (c0 - lft) / DXF;    // backward diff
            const float dpx = (rgt - c0) / DXF;    // forward diff
            const float dmy = (c0 - bel) / DXF;
            const float dpy = (abv - c0) / DXF;
            const float dmz = (c0 - bck) / DXF;
            const float dpz = (frt - c0) / DXF;

            const float gx_in  = (nx > 0.0f) ? dmx : dpx;
            const float gx_out = (nx > 0.0f) ? dpx : dmx;
            const float gy_in  = (ny > 0.0f) ? dmy : dpy;
            const float gy_out = (ny > 0.0f) ? dpy : dmy;
            const float gz_in  = (nz > 0.0f) ? dmz : dpz;
            const float gz_out = (nz > 0.0f) ? dpz : dmz;

            const float nd_in  = gx_in  * nx + gy_in  * ny + gz_in  * nz;
            const float nd_out = gx_out * nx + gy_out * ny + gz_out * nz;

            // E_IN = 1, E_OUT = 80
            const float t = (nd_in + gcnd) - 80.0f * nd_out;
            local = fmaf(t, t, local);
        }
    }

    // Block reduction: full-warp shuffle (non-leader lanes hold 0), then cross-warp
    float v = local;
    #pragma unroll
    for (int off = 16; off > 0; off >>= 1)
        v += __shfl_down_sync(0xffffffffu, v, off);

    __shared__ float wsum[8];
    const int warp = tid >> 5;
    const int lane = tid & 31;
    if (lane == 0) wsum[warp] = v;
    __syncthreads();

    if (warp == 0) {
        v = (lane < (int)(blockDim.x >> 5)) ? wsum[lane] : 0.0f;
        #pragma unroll
        for (int off = 4; off > 0; off >>= 1)
            v += __shfl_down_sync(0xffffffffu, v, off);
        if (lane == 0) {
            const float inv_den = 1.0f / (float)(BATCH * nb);
            atomicAdd(out, v * inv_den);
        }
    }
}

extern "C" void kernel_launch(void* const* d_in, const int* in_sizes, int n_in,
                              void* d_out, int out_size)
{
    const float* field   = (const float*)d_in[0];  // output (2,1,64,64,64)
    const float* q       = (const float*)d_in[1];  // (200,)
    const float* xq      = (const float*)d_in[2];  // (200,3)
    const float* points  = (const float*)d_in[3];  // (262144,3)
    const int*   xi      = (const int*)  d_in[4];
    const int*   yi      = (const int*)  d_in[5];
    const int*   zi      = (const int*)  d_in[6];
    const float* normals = (const float*)d_in[7];  // (NB,3)
    float*       out     = (float*)d_out;

    const int nb = in_sizes[4];

    // Zero the accumulator via a memset node (cheaper than a kernel launch)
    cudaMemsetAsync(out, 0, sizeof(float));

    const int threads = 256;
    const int total   = nb * CH;
    const int blocks  = (total + threads - 1) / threads;
    ibl_loss_kernel<<<blocks, threads>>>(field, q, xq, points,
                                         xi, yi, zi, normals, nb, out);
}

// round 5
// speedup vs baseline: 1.7022x; 1.1360x over previous
#include <cuda_runtime.h>
#include <math.h>

// Problem constants (fixed by the reference)
#define NN      64
#define GRID_N  (NN * NN * NN)   // 262144
#define NQ      200
#define BATCH   2
#define CH      8                // threads cooperating per boundary point
#define QPT     (NQ / CH)        // 25 charges per thread
#define MAXB    1024             // max blocks for scratch

// Scratch for cross-block reduction (allocation-free: __device__ globals)
__device__ float        g_partials[MAXB];
__device__ unsigned int g_ticket = 0;   // self-resetting via atomicInc wrap

__global__ __launch_bounds__(256)
void ibl_loss_kernel(const float* __restrict__ field,    // (BATCH,1,64,64,64)
                     const float* __restrict__ q,        // (NQ,)
                     const float* __restrict__ xq,       // (NQ,3)
                     const float* __restrict__ points,   // (GRID_N,3)
                     const int*   __restrict__ xi,
                     const int*   __restrict__ yi,
                     const int*   __restrict__ zi,
                     const float* __restrict__ normals,  // (NB,3)
                     int nb,
                     float* __restrict__ out)
{
    __shared__ float4 sq[NQ];   // {xq.x, xq.y, xq.z, q}
    __shared__ bool   s_is_last;

    const float EPSF   = 1.1920929e-07f;               // np.finfo(float32).eps
    const float INV4PI = 1.0f / (4.0f * 3.14159265358979323846f);
    const float DXF    = (float)(1.0 / 63.0);
    const float RDX    = 1.0f / DXF;                   // compile-time folded

    const int tid  = threadIdx.x;
    const int gtid = blockIdx.x * blockDim.x + tid;
    const int i    = gtid >> 3;        // boundary point index
    const int c    = gtid & (CH - 1);  // charge-chunk index within point
    const bool leader = (c == 0) && (i < nb);

    // ---- Hoisted leader loads: field stencil (both batches) + normals.
    // Issued first so their DRAM latency overlaps staging + the charge loop.
    float nx = 0.f, ny = 0.f, nz = 0.f;
    float c0[BATCH], lft[BATCH], rgt[BATCH], bel[BATCH], abv[BATCH], bck[BATCH], frt[BATCH];
    int flat = 0;
    if (i < nb) {
        const int x = xi[i], y = yi[i], z = zi[i];
        flat = (x * NN + y) * NN + z;
    }
    if (leader) {
        nx = normals[3 * i + 0];
        ny = normals[3 * i + 1];
        nz = normals[3 * i + 2];
        #pragma unroll
        for (int b = 0; b < BATCH; b++) {
            const float* __restrict__ o = field + b * GRID_N;
            c0[b]  = o[flat];
            lft[b] = o[flat - NN * NN];
            rgt[b] = o[flat + NN * NN];
            bel[b] = o[flat - NN];
            abv[b] = o[flat + NN];
            bck[b] = o[flat - 1];
            frt[b] = o[flat + 1];
        }
    } else {
        #pragma unroll
        for (int b = 0; b < BATCH; b++) {
            c0[b] = lft[b] = rgt[b] = bel[b] = abv[b] = bck[b] = frt[b] = 0.f;
        }
    }

    // ---- Stage charges into shared memory (one per thread, 200 <= 256)
    if (tid < NQ) {
        sq[tid] = make_float4(xq[3 * tid + 0], xq[3 * tid + 1], xq[3 * tid + 2], q[tid]);
    }
    __syncthreads();

    // ---- Green's function partial sums over this thread's 25 charges
    float g = 0.0f, gx = 0.0f, gy = 0.0f, gz = 0.0f;
    if (i < nb) {
        const float px = points[3 * flat + 0];
        const float py = points[3 * flat + 1];
        const float pz = points[3 * flat + 2];

        const int k0 = c * QPT;
        #pragma unroll
        for (int kk = 0; kk < QPT; kk++) {
            const float4 ch = sq[k0 + kk];
            const float dx = px - ch.x;
            const float dy = py - ch.y;
            const float dz = pz - ch.z;
            const float r2 = fmaf(dx, dx, fmaf(dy, dy, dz * dz));
            const float inv_r  = (r2 > 0.0f) ? rsqrtf(r2) : (1.0f / EPSF);
            g = fmaf(ch.w, inv_r, g);
            const float inv_r3 = inv_r * inv_r * inv_r;
            const float coef   = -ch.w * inv_r3;
            gx = fmaf(coef, dx, gx);
            gy = fmaf(coef, dy, gy);
            gz = fmaf(coef, dz, gz);
        }
    }

    // ---- Reduce 4 accumulators across the 8-thread group
    #pragma unroll
    for (int off = CH / 2; off > 0; off >>= 1) {
        g  += __shfl_down_sync(0xffffffffu, g,  off, CH);
        gx += __shfl_down_sync(0xffffffffu, gx, off, CH);
        gy += __shfl_down_sync(0xffffffffu, gy, off, CH);
        gz += __shfl_down_sync(0xffffffffu, gz, off, CH);
    }

    float local = 0.0f;
    if (leader) {
        g  *= INV4PI;
        gx *= INV4PI;
        gy *= INV4PI;
        gz *= INV4PI;

        const float gcnd = gx * nx + gy * ny + gz * nz;

        // loss1: (mol_b - out_b)^2 == g^2, identical for both batches
        local = (float)BATCH * (g * g);

        // loss2: one-sided normal derivatives per batch (preloaded stencil)
        #pragma unroll
        for (int b = 0; b < BATCH; b++) {
            const float dmx = (c0[b]  - lft[b]) * RDX;
            const float dpx = (rgt[b] - c0[b])  * RDX;
            const float dmy = (c0[b]  - bel[b]) * RDX;
            const float dpy = (abv[b] - c0[b])  * RDX;
            const float dmz = (c0[b]  - bck[b]) * RDX;
            const float dpz = (frt[b] - c0[b])  * RDX;

            const float gx_in  = (nx > 0.0f) ? dmx : dpx;
            const float gx_out = (nx > 0.0f) ? dpx : dmx;
            const float gy_in  = (ny > 0.0f) ? dmy : dpy;
            const float gy_out = (ny > 0.0f) ? dpy : dmy;
            const float gz_in  = (nz > 0.0f) ? dmz : dpz;
            const float gz_out = (nz > 0.0f) ? dpz : dmz;

            const float nd_in  = gx_in  * nx + gy_in  * ny + gz_in  * nz;
            const float nd_out = gx_out * nx + gy_out * ny + gz_out * nz;

            // E_IN = 1, E_OUT = 80
            const float t = (nd_in + gcnd) - 80.0f * nd_out;
            local = fmaf(t, t, local);
        }
    }

    // ---- Block reduction
    float v = local;
    #pragma unroll
    for (int off = 16; off > 0; off >>= 1)
        v += __shfl_down_sync(0xffffffffu, v, off);

    __shared__ float wsum[8];
    const int warp = tid >> 5;
    const int lane = tid & 31;
    if (lane == 0) wsum[warp] = v;
    __syncthreads();

    if (warp == 0) {
        v = (lane < (int)(blockDim.x >> 5)) ? wsum[lane] : 0.0f;
        #pragma unroll
        for (int off = 4; off > 0; off >>= 1)
            v += __shfl_down_sync(0xffffffffu, v, off);
    }

    // ---- Cross-block: last block reduces all partials (self-resetting ticket)
    const int nblocks = gridDim.x;
    if (tid == 0) {
        g_partials[blockIdx.x] = v;
        __threadfence();
        // atomicInc wraps to 0 after nblocks increments -> self-resetting
        unsigned int t = atomicInc(&g_ticket, (unsigned int)(nblocks - 1));
        s_is_last = (t == (unsigned int)(nblocks - 1));
    }
    __syncthreads();

    if (s_is_last && warp == 0) {
        const volatile float* vp = g_partials;   // force L2 reads (post-fence)
        float s = 0.0f;
        for (int j = lane; j < nblocks; j += 32)
            s += vp[j];
        #pragma unroll
        for (int off = 16; off > 0; off >>= 1)
            s += __shfl_down_sync(0xffffffffu, s, off);
        if (lane == 0) {
            const float inv_den = 1.0f / (float)(BATCH * nb);
            out[0] = s * inv_den;
        }
    }
}

extern "C" void kernel_launch(void* const* d_in, const int* in_sizes, int n_in,
                              void* d_out, int out_size)
{
    const float* field   = (const float*)d_in[0];  // output (2,1,64,64,64)
    const float* q       = (const float*)d_in[1];  // (200,)
    const float* xq      = (const float*)d_in[2];  // (200,3)
    const float* points  = (const float*)d_in[3];  // (262144,3)
    const int*   xi      = (const int*)  d_in[4];
    const int*   yi      = (const int*)  d_in[5];
    const int*   zi      = (const int*)  d_in[6];
    const float* normals = (const float*)d_in[7];  // (NB,3)
    float*       out     = (float*)d_out;

    const int nb = in_sizes[4];

    const int threads = 256;
    const int total   = nb * CH;
    int blocks        = (total + threads - 1) / threads;
    if (blocks > MAXB) blocks = MAXB;   // safety (nb ~ 4.7K -> 147 blocks)

    ibl_loss_kernel<<<blocks, threads>>>(field, q, xq, points,
                                         xi, yi, zi, normals, nb, out);
}